// round 14
// baseline (speedup 1.0000x reference)
#include <cuda_runtime.h>

#define W_IMG 2048
#define H_IMG 2048
#define NPIX (W_IMG * H_IMG)
#define WW 64                     // 32-bit words per image row
#define NWORDS (WW * H_IMG)

__device__ unsigned g_W[NWORDS];   // weak-or-strong candidate mask
__device__ unsigned g_E[NWORDS];   // edge mask (strong seeds -> final edges)

// cooperative-kernel state (self-restoring across graph replays)
__device__ unsigned g_bar_arrive;
__device__ unsigned g_bar_gen;
__device__ unsigned g_flag3[3];

__device__ __forceinline__ unsigned dilw(unsigned l, unsigned m, unsigned r) {
    return m | (m << 1) | (m >> 1) | (l >> 31) | (r << 31);
}

__device__ __forceinline__ unsigned hclose(unsigned s, unsigned W) {
    unsigned up = W & ((W + s) ^ W);
    unsigned rs = __brev(s), rW = __brev(W);
    unsigned dn = __brev(rW & ((rW + rs) ^ rW));
    return s | up | dn;
}

// input is uniform [0,1): floor(x*255) in [0,254] -> no clamps needed
__device__ __forceinline__ float quant(float v) { return floorf(v * 255.0f); }
__device__ __forceinline__ float4 quant4(float4 v) {
    return make_float4(floorf(v.x * 255.0f), floorf(v.y * 255.0f),
                       floorf(v.z * 255.0f), floorf(v.w * 255.0f));
}

// ---------------------------------------------------------------------------
// K1: streaming Sobel + NMS, 4 cols/thread. Production-time NMS split:
// n1 (rows p-1/p) and the s=0 n2 are resolved when a row's mags are produced;
// only the row-p+1 n2 compare is deferred. Carries ONE mag row + 1 bits reg.
// (R13 version, isolated this round)
// ---------------------------------------------------------------------------
#define GR 8

__global__ __launch_bounds__(128, 9) void k_grad(const float* __restrict__ x) {
    const unsigned FULL = 0xFFFFFFFFu;
    const int lane = threadIdx.x & 31;
    const int gw = blockIdx.x * 4 + (threadIdx.x >> 5);
    const int strip = gw & 15;             // 16 strips of 128 cols
    const int rg = gw >> 4;                // 256 row groups of 8 rows
    const int c0 = strip * 128;
    const int y0 = rg * GR;
    const int col = c0 + lane * 4;

    const bool bl = (lane == 0), br = (lane == 31);
    const bool he = bl || br;
    const int xh0 = bl ? max(c0 - 2, 0) : min(c0 + 128, W_IMG - 1);
    const int xh1 = bl ? max(c0 - 1, 0) : min(c0 + 129, W_IMG - 1);

    const float T1 = 0.41421356237309503f;  // tan(22.5)
    const float T2 = 2.41421356237309510f;  // tan(67.5)

    const int ra = max(y0 - 2, 0), rb = max(y0 - 1, 0);
    const float4* xv = reinterpret_cast<const float4*>(x);
    const int cv = col >> 2;

    float4 A = quant4(__ldg(&xv[ra * (W_IMG / 4) + cv]));
    float4 B = quant4(__ldg(&xv[rb * (W_IMG / 4) + cv]));
    float4 C = quant4(__ldg(&xv[y0 * (W_IMG / 4) + cv]));
    float Ah0 = 0, Ah1 = 0, Bh0 = 0, Bh1 = 0, Ch0 = 0, Ch1 = 0;
    if (he) {
        Ah0 = quant(__ldg(&x[ra * W_IMG + xh0]));
        Ah1 = quant(__ldg(&x[ra * W_IMG + xh1]));
        Bh0 = quant(__ldg(&x[rb * W_IMG + xh0]));
        Bh1 = quant(__ldg(&x[rb * W_IMG + xh1]));
        Ch0 = quant(__ldg(&x[y0 * W_IMG + xh0]));
        Ch1 = quant(__ldg(&x[y0 * W_IMG + xh1]));
    }

    float pMm1 = 0, pM0 = 0, pM1 = 0, pM2 = 0, pM3 = 0, pMp4 = 0;
    unsigned bits = 0;

    const bool ic0 = (col + 0 >= 1) && (col + 0 <= W_IMG - 2);
    const bool ic3 = (col + 3 >= 1) && (col + 3 <= W_IMG - 2);

#pragma unroll
    for (int i = 0; i < GR + 2; i++) {
        const int m = y0 - 1 + i;
        const int yn = min(m + 2, H_IMG - 1);
        float4 N = quant4(__ldg(&xv[yn * (W_IMG / 4) + cv]));
        float Nh0 = 0, Nh1 = 0;
        if (he) {
            Nh0 = quant(__ldg(&x[yn * W_IMG + xh0]));
            Nh1 = quant(__ldg(&x[yn * W_IMG + xh1]));
        }

        float t1x = A.x + 2.0f * B.x + C.x, t2x = C.x - A.x;
        float t1y = A.y + 2.0f * B.y + C.y, t2y = C.y - A.y;
        float t1z = A.z + 2.0f * B.z + C.z, t2z = C.z - A.z;
        float t1w = A.w + 2.0f * B.w + C.w, t2w = C.w - A.w;
        float t1h0 = Ah0 + 2.0f * Bh0 + Ch0, t2h0 = Ch0 - Ah0;
        float t1h1 = Ah1 + 2.0f * Bh1 + Ch1, t2h1 = Ch1 - Ah1;

        float t1m1 = __shfl_up_sync(FULL, t1w, 1);
        float t2m1 = __shfl_up_sync(FULL, t2w, 1);
        float t1p4 = __shfl_down_sync(FULL, t1x, 1);
        float t2p4 = __shfl_down_sync(FULL, t2x, 1);
        if (bl) { t1m1 = t1h1; t2m1 = t2h1; }
        if (br) { t1p4 = t1h0; t2p4 = t2h0; }

        float gx0 = t1y - t1m1, gy0 = t2m1 + 2.0f * t2x + t2y;
        float gx1 = t1z - t1x,  gy1 = t2x + 2.0f * t2y + t2z;
        float gx2 = t1w - t1y,  gy2 = t2y + 2.0f * t2z + t2w;
        float gx3 = t1p4 - t1z, gy3 = t2z + 2.0f * t2w + t2p4;
        float m0 = fabsf(gx0) + fabsf(gy0);
        float m1 = fabsf(gx1) + fabsf(gy1);
        float m2 = fabsf(gx2) + fabsf(gy2);
        float m3 = fabsf(gx3) + fabsf(gy3);

        float magH = 0.0f;
        if (bl) magH = fabsf(t1x - t1h0) + fabsf(t2h0 + 2.0f * t2h1 + t2x);
        if (br) magH = fabsf(t1h1 - t1w) + fabsf(t2w + 2.0f * t2h0 + t2h1);

        float mm1 = __shfl_up_sync(FULL, m3, 1);
        float mp4 = __shfl_down_sync(FULL, m0, 1);
        if (bl) mm1 = magH;
        if (br) mp4 = magH;

        // ---- consumption: finalize row p = m-1 (n2 from this fresh row) ----
        if (i >= 2) {
            const int p = m - 1;
            unsigned wn = 0, sn = 0;
            {
                unsigned s = bits & 3u;
                float n2 = (s == 1u) ? m0 : (s == 2u) ? mm1 : (s == 3u) ? m1 : -1.0f;
                bool ok = pM0 > n2;
                if (ok && (bits & 0x00010000u)) wn |= 1u;
                if (ok && (bits & 0x01000000u)) sn |= 1u;
            }
            {
                unsigned s = (bits >> 2) & 3u;
                float n2 = (s == 1u) ? m1 : (s == 2u) ? m0 : (s == 3u) ? m2 : -1.0f;
                bool ok = pM1 > n2;
                if (ok && (bits & 0x00020000u)) wn |= 2u;
                if (ok && (bits & 0x02000000u)) sn |= 2u;
            }
            {
                unsigned s = (bits >> 4) & 3u;
                float n2 = (s == 1u) ? m2 : (s == 2u) ? m1 : (s == 3u) ? m3 : -1.0f;
                bool ok = pM2 > n2;
                if (ok && (bits & 0x00040000u)) wn |= 4u;
                if (ok && (bits & 0x04000000u)) sn |= 4u;
            }
            {
                unsigned s = (bits >> 6) & 3u;
                float n2 = (s == 1u) ? m3 : (s == 2u) ? m2 : (s == 3u) ? mp4 : -1.0f;
                bool ok = pM3 > n2;
                if (ok && (bits & 0x00080000u)) wn |= 8u;
                if (ok && (bits & 0x08000000u)) sn |= 8u;
            }

            unsigned sh = (lane & 3u) * 4u;
            unsigned v = (wn << sh) | (sn << (sh + 16));
            v |= __shfl_xor_sync(FULL, v, 1);
            v |= __shfl_xor_sync(FULL, v, 2);
            unsigned vp = __shfl_xor_sync(FULL, v, 4);
            if ((lane & 7) == 0) {
                unsigned wword = (v & 0xFFFFu) | (vp << 16);
                unsigned sword = (v >> 16) | (vp & 0xFFFF0000u);
                int wi = p * WW + strip * 4 + (lane >> 3);
                g_W[wi] = wword;
                g_E[wi] = sword;
            }
        }

        // ---- production for row m: dir code, n1 (rows m-1/m), thresholds ----
        if (i <= GR) {
            const bool irm = (m >= 1) && (m <= H_IMG - 2);
            unsigned nb = 0;
            {
                float ag = fabsf(gx0), ah = fabsf(gy0);
                unsigned s = (ah < ag * T1) ? 0u : (ah > ag * T2) ? 1u
                           : (gx0 * gy0 > 0.0f) ? 2u : 3u;
                float n1 = (s == 0u) ? m1 : (s == 1u) ? pM0 : (s == 2u) ? pM1 : pMm1;
                bool c1 = (m0 >= n1) && (s != 0u || m0 > mm1) && irm && ic0;
                nb |= s;
                if (c1 && m0 > 100.0f) nb |= 0x00010000u;
                if (c1 && m0 > 200.0f) nb |= 0x01000000u;
            }
            {
                float ag = fabsf(gx1), ah = fabsf(gy1);
                unsigned s = (ah < ag * T1) ? 0u : (ah > ag * T2) ? 1u
                           : (gx1 * gy1 > 0.0f) ? 2u : 3u;
                float n1 = (s == 0u) ? m2 : (s == 1u) ? pM1 : (s == 2u) ? pM2 : pM0;
                bool c1 = (m1 >= n1) && (s != 0u || m1 > m0) && irm;
                nb |= s << 2;
                if (c1 && m1 > 100.0f) nb |= 0x00020000u;
                if (c1 && m1 > 200.0f) nb |= 0x02000000u;
            }
            {
                float ag = fabsf(gx2), ah = fabsf(gy2);
                unsigned s = (ah < ag * T1) ? 0u : (ah > ag * T2) ? 1u
                           : (gx2 * gy2 > 0.0f) ? 2u : 3u;
                float n1 = (s == 0u) ? m3 : (s == 1u) ? pM2 : (s == 2u) ? pM3 : pM1;
                bool c1 = (m2 >= n1) && (s != 0u || m2 > m1) && irm;
                nb |= s << 4;
                if (c1 && m2 > 100.0f) nb |= 0x00040000u;
                if (c1 && m2 > 200.0f) nb |= 0x04000000u;
            }
            {
                float ag = fabsf(gx3), ah = fabsf(gy3);
                unsigned s = (ah < ag * T1) ? 0u : (ah > ag * T2) ? 1u
                           : (gx3 * gy3 > 0.0f) ? 2u : 3u;
                float n1 = (s == 0u) ? mp4 : (s == 1u) ? pM3 : (s == 2u) ? pMp4 : pM2;
                bool c1 = (m3 >= n1) && (s != 0u || m3 > m2) && irm && ic3;
                nb |= s << 6;
                if (c1 && m3 > 100.0f) nb |= 0x00080000u;
                if (c1 && m3 > 200.0f) nb |= 0x08000000u;
            }
            bits = nb;
        }

        pMm1 = mm1; pM0 = m0; pM1 = m1; pM2 = m2; pM3 = m3; pMp4 = mp4;
        A = B; B = C; C = N;
        Ah0 = Bh0; Bh0 = Ch0; Ch0 = Nh0;
        Ah1 = Bh1; Bh1 = Ch1; Ch1 = Nh1;
    }
}

// ---------------------------------------------------------------------------
// K2: persistent cooperative hysteresis (R11 proven shape).
// 32 blocks x 64-row bands, 1024 threads, 4 rows/thread Gauss-Seidel;
// 3-phase rotating flags, one grid barrier per round; hclose-seeded load.
// ---------------------------------------------------------------------------
#define BAND 64
#define NB (H_IMG / BAND)   // 32

__device__ __forceinline__ void grid_barrier() {
    __syncthreads();
    if (threadIdx.x == 0) {
        __threadfence();
        unsigned gen = *(volatile unsigned*)&g_bar_gen;
        unsigned a = atomicAdd(&g_bar_arrive, 1u);
        if (a == NB - 1) {
            g_bar_arrive = 0u;
            __threadfence();
            atomicAdd(&g_bar_gen, 1u);
        } else {
            while (*(volatile unsigned*)&g_bar_gen == gen) __nanosleep(20);
        }
        __threadfence();
    }
    __syncthreads();
}

__global__ __launch_bounds__(1024, 1) void k_hyst() {
    __shared__ unsigned sE[BAND + 2][WW + 2];

    const int tid = threadIdx.x;
    const int q = tid >> 6, c = tid & 63;
    const int cc = c + 1;
    const int R = q * 4 + 1;
    const int r0 = blockIdx.x * BAND;
    const int gw = (r0 + q * 4) * WW + c;

    if (tid < BAND + 2) { sE[tid][0] = 0u; sE[tid][WW + 1] = 0u; }
    if (tid < WW) { sE[0][tid + 1] = 0u; sE[BAND + 1][tid + 1] = 0u; }

    const unsigned W0 = g_W[gw];
    const unsigned W1 = g_W[gw + WW];
    const unsigned W2 = g_W[gw + 2 * WW];
    const unsigned W3 = g_W[gw + 3 * WW];
    unsigned v0 = hclose(g_E[gw], W0);
    unsigned v1 = hclose(g_E[gw + WW], W1);
    unsigned v2 = hclose(g_E[gw + 2 * WW], W2);
    unsigned v3 = hclose(g_E[gw + 3 * WW], W3);
    sE[R][cc] = v0; sE[R + 1][cc] = v1; sE[R + 2][cc] = v2; sE[R + 3][cc] = v3;
    __syncthreads();

    auto pass = [&]() -> int {
        unsigned up = dilw(sE[R - 1][cc - 1], sE[R - 1][cc], sE[R - 1][cc + 1]);
        unsigned dn = dilw(sE[R + 4][cc - 1], sE[R + 4][cc], sE[R + 4][cc + 1]);
        unsigned h0 = dilw(sE[R + 0][cc - 1], v0, sE[R + 0][cc + 1]);
        unsigned h1 = dilw(sE[R + 1][cc - 1], v1, sE[R + 1][cc + 1]);
        unsigned h2 = dilw(sE[R + 2][cc - 1], v2, sE[R + 2][cc + 1]);
        unsigned h3 = dilw(sE[R + 3][cc - 1], v3, sE[R + 3][cc + 1]);
        unsigned n0 = hclose(v0 | (W0 & (up | h0 | h1)), W0);
        h0 = dilw(sE[R + 0][cc - 1], n0, sE[R + 0][cc + 1]);
        unsigned n1 = hclose(v1 | (W1 & (h0 | h1 | h2)), W1);
        h1 = dilw(sE[R + 1][cc - 1], n1, sE[R + 1][cc + 1]);
        unsigned n2 = hclose(v2 | (W2 & (h1 | h2 | h3)), W2);
        h2 = dilw(sE[R + 2][cc - 1], n2, sE[R + 2][cc + 1]);
        unsigned n3 = hclose(v3 | (W3 & (h2 | h3 | dn)), W3);
        h3 = dilw(sE[R + 3][cc - 1], n3, sE[R + 3][cc + 1]);
        n2 = hclose(n2 | (W2 & (h1 | h2 | h3)), W2);
        h2 = dilw(sE[R + 2][cc - 1], n2, sE[R + 2][cc + 1]);
        n1 = hclose(n1 | (W1 & (h0 | h1 | h2)), W1);
        h1 = dilw(sE[R + 1][cc - 1], n1, sE[R + 1][cc + 1]);
        n0 = hclose(n0 | (W0 & (up | h0 | h1)), W0);

        int ch = (n0 != v0) | (n1 != v1) | (n2 != v2) | (n3 != v3);
        if (n0 != v0) { v0 = n0; sE[R][cc] = v0; }
        if (n1 != v1) { v1 = n1; sE[R + 1][cc] = v1; }
        if (n2 != v2) { v2 = n2; sE[R + 2][cc] = v2; }
        if (n3 != v3) { v3 = n3; sE[R + 3][cc] = v3; }
        return __syncthreads_or(ch);
    };

    while (pass()) {}   // initial local fixpoint

    for (int r = 0;; r++) {
        if (q == 0)  *(volatile unsigned*)&g_E[r0 * WW + c] = v0;
        if (q == 15) *(volatile unsigned*)&g_E[(r0 + BAND - 1) * WW + c] = v3;
        grid_barrier();

        if (blockIdx.x == 0 && tid == 0) g_flag3[(r + 1) % 3] = 0u;  // pre-reset
        if (r > 0) {
            unsigned f = *(volatile unsigned*)&g_flag3[(r - 1) % 3];
            if (!f) break;
        }

        if (tid < WW) {
            sE[0][tid + 1] = (r0 > 0) ? *(volatile unsigned*)&g_E[(r0 - 1) * WW + tid] : 0u;
            sE[BAND + 1][tid + 1] = (r0 + BAND < H_IMG)
                ? *(volatile unsigned*)&g_E[(r0 + BAND) * WW + tid] : 0u;
        }
        __syncthreads();

        int changed = pass();
        if (changed) {
            if (tid == 0) atomicOr(&g_flag3[r % 3], 1u);
            while (pass()) {}
        }
    }

    g_E[gw] = v0;
    g_E[gw + WW] = v1;
    g_E[gw + 2 * WW] = v2;
    g_E[gw + 3 * WW] = v3;
}

// ---------------------------------------------------------------------------
// K3: expand edge bitmask -> 3 x H x W float via smem staging + TMA bulk.
// ---------------------------------------------------------------------------
#define WRB 2

__global__ __launch_bounds__(256) void k_write(float* __restrict__ out) {
    __shared__ __align__(16) float4 sbuf[WRB * 512];   // 16 KB

    const int r0 = blockIdx.x * WRB;
    const int t = threadIdx.x;

#pragma unroll
    for (int k = 0; k < WRB * 2; k++) {
        int f = t + k * 256;
        int row = f >> 9;
        int x4 = f & 511;
        unsigned w = g_E[(r0 + row) * WW + (x4 >> 3)];
        unsigned bits = (w >> ((x4 & 7u) * 4u)) & 0xFu;
        float4 v;
        v.x = (bits & 1u) ? 1.0f : 0.0f;
        v.y = (bits & 2u) ? 1.0f : 0.0f;
        v.z = (bits & 4u) ? 1.0f : 0.0f;
        v.w = (bits & 8u) ? 1.0f : 0.0f;
        sbuf[f] = v;
    }
    __syncthreads();

    if (t == 0) {
        asm volatile("fence.proxy.async.shared::cta;" ::: "memory");
        unsigned saddr = (unsigned)__cvta_generic_to_shared(sbuf);
#pragma unroll
        for (int plane = 0; plane < 3; plane++) {
            float* dst = out + (size_t)plane * NPIX + (size_t)r0 * W_IMG;
            asm volatile(
                "cp.async.bulk.global.shared::cta.bulk_group [%0], [%1], %2;"
                :: "l"(dst), "r"(saddr), "n"(WRB * W_IMG * 4) : "memory");
        }
        asm volatile("cp.async.bulk.commit_group;" ::: "memory");
        asm volatile("cp.async.bulk.wait_group 0;" ::: "memory");
    }
}

// ---------------------------------------------------------------------------
extern "C" void kernel_launch(void* const* d_in, const int* in_sizes, int n_in,
                              void* d_out, int out_size) {
    const float* x = (const float*)d_in[0];
    float* out = (float*)d_out;

    k_grad<<<1024, 128>>>(x);
    k_hyst<<<NB, 1024>>>();
    k_write<<<H_IMG / WRB, 256>>>(out);
}

// round 15
// speedup vs baseline: 1.1056x; 1.1056x over previous
#include <cuda_runtime.h>

#define W_IMG 2048
#define H_IMG 2048
#define NPIX (W_IMG * H_IMG)
#define WW 64                      // 32-bit words per image row
#define BAND 16
#define NB (H_IMG / BAND)          // 128 CTAs, one wave

__device__ unsigned g_E[WW * H_IMG];   // boundary-row exchange only
__device__ unsigned g_bar_arrive;      // self-restoring barrier state
__device__ unsigned g_bar_gen;
__device__ unsigned g_flag3[3];

__device__ __forceinline__ unsigned dilw(unsigned l, unsigned m, unsigned r) {
    return m | (m << 1) | (m >> 1) | (l >> 31) | (r << 31);
}

__device__ __forceinline__ unsigned hclose(unsigned s, unsigned W) {
    unsigned up = W & ((W + s) ^ W);
    unsigned rs = __brev(s), rW = __brev(W);
    unsigned dn = __brev(rW & ((rW + rs) ^ rW));
    return s | up | dn;
}

// input uniform [0,1): floor(x*255) in [0,254] -> no clamps needed
__device__ __forceinline__ float quant(float v) { return floorf(v * 255.0f); }
__device__ __forceinline__ float4 quant4(float4 v) {
    return make_float4(floorf(v.x * 255.0f), floorf(v.y * 255.0f),
                       floorf(v.z * 255.0f), floorf(v.w * 255.0f));
}

__device__ __forceinline__ void grid_barrier() {
    __syncthreads();
    if (threadIdx.x == 0) {
        __threadfence();
        unsigned gen = *(volatile unsigned*)&g_bar_gen;
        unsigned a = atomicAdd(&g_bar_arrive, 1u);
        if (a == NB - 1) {
            g_bar_arrive = 0u;
            __threadfence();
            atomicAdd(&g_bar_gen, 1u);
        } else {
            while (*(volatile unsigned*)&g_bar_gen == gen) __nanosleep(20);
        }
        __threadfence();
    }
    __syncthreads();
}

// ---------------------------------------------------------------------------
// Fused kernel: grad (R11 warp code) -> in-smem hysteresis -> TMA writeout.
// 128 CTAs x 1024 threads; CTA b owns rows [16b, 16b+16).
// ---------------------------------------------------------------------------
#define GR 8

__global__ __launch_bounds__(1024, 1) void k_fused(const float* __restrict__ x,
                                                   float* __restrict__ out) {
    __shared__ unsigned sE[BAND + 2][WW + 2];
    __shared__ unsigned sW[BAND][WW];
    __shared__ __align__(16) float4 sbuf[2][1024];   // 2 x 16 KB staging

    const unsigned FULL = 0xFFFFFFFFu;
    const int tid = threadIdx.x;
    const int lane = tid & 31;
    const int warp = tid >> 5;
    const int r0 = blockIdx.x * BAND;

    // zero sE halos (rows 0/17, cols 0/65)
    if (tid < BAND + 2) { sE[tid][0] = 0u; sE[tid][WW + 1] = 0u; }
    if (tid < WW) { sE[0][tid + 1] = 0u; sE[BAND + 1][tid + 1] = 0u; }

    // =============== PHASE 1: gradient + NMS (R11 warp code) ===============
    {
        const int strip = warp & 15;           // 16 strips of 128 cols
        const int half = warp >> 4;            // 2 row-halves of 8 rows
        const int c0 = strip * 128;
        const int y0 = r0 + half * GR;
        const int col = c0 + lane * 4;

        const bool bl = (lane == 0), br = (lane == 31);
        const bool he = bl || br;
        const int xh0 = bl ? max(c0 - 2, 0) : min(c0 + 128, W_IMG - 1);
        const int xh1 = bl ? max(c0 - 1, 0) : min(c0 + 129, W_IMG - 1);

        const float T1 = 0.41421356237309503f;  // tan(22.5)
        const float T2 = 2.41421356237309510f;  // tan(67.5)

        const int ra = max(y0 - 2, 0), rb = max(y0 - 1, 0);
        const float4* xv = reinterpret_cast<const float4*>(x);
        const int cv = col >> 2;

        float4 A = quant4(__ldg(&xv[ra * (W_IMG / 4) + cv]));
        float4 B = quant4(__ldg(&xv[rb * (W_IMG / 4) + cv]));
        float4 C = quant4(__ldg(&xv[y0 * (W_IMG / 4) + cv]));
        float Ah0 = 0, Ah1 = 0, Bh0 = 0, Bh1 = 0, Ch0 = 0, Ch1 = 0;
        if (he) {
            Ah0 = quant(__ldg(&x[ra * W_IMG + xh0]));
            Ah1 = quant(__ldg(&x[ra * W_IMG + xh1]));
            Bh0 = quant(__ldg(&x[rb * W_IMG + xh0]));
            Bh1 = quant(__ldg(&x[rb * W_IMG + xh1]));
            Ch0 = quant(__ldg(&x[y0 * W_IMG + xh0]));
            Ch1 = quant(__ldg(&x[y0 * W_IMG + xh1]));
        }

        float mU0 = 0, mU1 = 0, mU2 = 0, mU3 = 0, mUm1 = 0, mUp4 = 0;
        float mC0 = 0, mC1 = 0, mC2 = 0, mC3 = 0, mCm1 = 0, mCp4 = 0;
        unsigned selC = 0;

        const bool ic0 = (col + 0 >= 1) && (col + 0 <= W_IMG - 2);
        const bool ic3 = (col + 3 >= 1) && (col + 3 <= W_IMG - 2);

#pragma unroll
        for (int i = 0; i < GR + 2; i++) {
            const int m = y0 - 1 + i;
            const int yn = min(m + 2, H_IMG - 1);
            float4 N = quant4(__ldg(&xv[yn * (W_IMG / 4) + cv]));
            float Nh0 = 0, Nh1 = 0;
            if (he) {
                Nh0 = quant(__ldg(&x[yn * W_IMG + xh0]));
                Nh1 = quant(__ldg(&x[yn * W_IMG + xh1]));
            }

            float t1x = A.x + 2.0f * B.x + C.x, t2x = C.x - A.x;
            float t1y = A.y + 2.0f * B.y + C.y, t2y = C.y - A.y;
            float t1z = A.z + 2.0f * B.z + C.z, t2z = C.z - A.z;
            float t1w = A.w + 2.0f * B.w + C.w, t2w = C.w - A.w;
            float t1h0 = Ah0 + 2.0f * Bh0 + Ch0, t2h0 = Ch0 - Ah0;
            float t1h1 = Ah1 + 2.0f * Bh1 + Ch1, t2h1 = Ch1 - Ah1;

            float t1m1 = __shfl_up_sync(FULL, t1w, 1);
            float t2m1 = __shfl_up_sync(FULL, t2w, 1);
            float t1p4 = __shfl_down_sync(FULL, t1x, 1);
            float t2p4 = __shfl_down_sync(FULL, t2x, 1);
            if (bl) { t1m1 = t1h1; t2m1 = t2h1; }
            if (br) { t1p4 = t1h0; t2p4 = t2h0; }

            float gx0 = t1y - t1m1, gy0 = t2m1 + 2.0f * t2x + t2y;
            float gx1 = t1z - t1x,  gy1 = t2x + 2.0f * t2y + t2z;
            float gx2 = t1w - t1y,  gy2 = t2y + 2.0f * t2z + t2w;
            float gx3 = t1p4 - t1z, gy3 = t2z + 2.0f * t2w + t2p4;
            float m0 = fabsf(gx0) + fabsf(gy0);
            float m1 = fabsf(gx1) + fabsf(gy1);
            float m2 = fabsf(gx2) + fabsf(gy2);
            float m3 = fabsf(gx3) + fabsf(gy3);

            unsigned selN;
            {
                unsigned s0, s1, s2, s3;
                float ag, ah;
                ag = fabsf(gx0); ah = fabsf(gy0);
                s0 = (ah < ag * T1) ? 0u : (ah > ag * T2) ? 1u : (gx0 * gy0 > 0.0f) ? 2u : 3u;
                ag = fabsf(gx1); ah = fabsf(gy1);
                s1 = (ah < ag * T1) ? 0u : (ah > ag * T2) ? 1u : (gx1 * gy1 > 0.0f) ? 2u : 3u;
                ag = fabsf(gx2); ah = fabsf(gy2);
                s2 = (ah < ag * T1) ? 0u : (ah > ag * T2) ? 1u : (gx2 * gy2 > 0.0f) ? 2u : 3u;
                ag = fabsf(gx3); ah = fabsf(gy3);
                s3 = (ah < ag * T1) ? 0u : (ah > ag * T2) ? 1u : (gx3 * gy3 > 0.0f) ? 2u : 3u;
                selN = s0 | (s1 << 2) | (s2 << 4) | (s3 << 6);
            }

            float magH = 0.0f;
            if (bl) magH = fabsf(t1x - t1h0) + fabsf(t2h0 + 2.0f * t2h1 + t2x);
            if (br) magH = fabsf(t1h1 - t1w) + fabsf(t2w + 2.0f * t2h0 + t2h1);

            float mm1 = __shfl_up_sync(FULL, m3, 1);
            float mp4 = __shfl_down_sync(FULL, m0, 1);
            if (bl) mm1 = magH;
            if (br) mp4 = magH;

            if (i >= 2) {
                const int p = m - 1;
                const bool ir = (p >= 1) && (p <= H_IMG - 2);
                unsigned wn = 0, sn = 0;
                unsigned s;
                float n1, n2, mg;

                s = selC & 3u; mg = mC0;
                n1 = (s == 0) ? mC1 : (s == 1) ? mU0 : (s == 2) ? mU1 : mUm1;
                n2 = (s == 0) ? mCm1 : (s == 1) ? m0 : (s == 2) ? mm1 : m1;
                if (ir && ic0 && (mg >= n1) && (mg > n2) && mg > 100.0f) {
                    wn |= 1u; if (mg > 200.0f) sn |= 1u;
                }
                s = (selC >> 2) & 3u; mg = mC1;
                n1 = (s == 0) ? mC2 : (s == 1) ? mU1 : (s == 2) ? mU2 : mU0;
                n2 = (s == 0) ? mC0 : (s == 1) ? m1 : (s == 2) ? m0 : m2;
                if (ir && (mg >= n1) && (mg > n2) && mg > 100.0f) {
                    wn |= 2u; if (mg > 200.0f) sn |= 2u;
                }
                s = (selC >> 4) & 3u; mg = mC2;
                n1 = (s == 0) ? mC3 : (s == 1) ? mU2 : (s == 2) ? mU3 : mU1;
                n2 = (s == 0) ? mC1 : (s == 1) ? m2 : (s == 2) ? m1 : m3;
                if (ir && (mg >= n1) && (mg > n2) && mg > 100.0f) {
                    wn |= 4u; if (mg > 200.0f) sn |= 4u;
                }
                s = (selC >> 6) & 3u; mg = mC3;
                n1 = (s == 0) ? mCp4 : (s == 1) ? mU3 : (s == 2) ? mUp4 : mU2;
                n2 = (s == 0) ? mC2 : (s == 1) ? m3 : (s == 2) ? m2 : mp4;
                if (ir && ic3 && (mg >= n1) && (mg > n2) && mg > 100.0f) {
                    wn |= 8u; if (mg > 200.0f) sn |= 8u;
                }

                unsigned sh = (lane & 3u) * 4u;
                unsigned v = (wn << sh) | (sn << (sh + 16));
                v |= __shfl_xor_sync(FULL, v, 1);
                v |= __shfl_xor_sync(FULL, v, 2);
                unsigned vp = __shfl_xor_sync(FULL, v, 4);
                if ((lane & 7) == 0) {
                    unsigned wword = (v & 0xFFFFu) | (vp << 16);
                    unsigned sword = (v >> 16) | (vp & 0xFFFF0000u);
                    int rr = p - r0;                       // 0..15
                    int wc = strip * 4 + (lane >> 3);      // 0..63
                    sW[rr][wc] = wword;
                    sE[rr + 1][wc + 1] = sword;
                }
            }

            mUm1 = mCm1; mU0 = mC0; mU1 = mC1; mU2 = mC2; mU3 = mC3; mUp4 = mCp4;
            mCm1 = mm1;  mC0 = m0;  mC1 = m1;  mC2 = m2;  mC3 = m3;  mCp4 = mp4;
            selC = selN;
            A = B; B = C; C = N;
            Ah0 = Bh0; Bh0 = Ch0; Ch0 = Nh0;
            Ah1 = Bh1; Bh1 = Ch1; Ch1 = Nh1;
        }
    }
    __syncthreads();

    // =============== PHASE 2: in-smem hysteresis fixpoint ===============
    const int row = tid >> 6, c = tid & 63;    // 16 rows x 64 words
    const int R = row + 1, cc = c + 1;
    unsigned v = sE[R][cc];
    const unsigned Wm = sW[row][c];

    auto pass = [&]() -> int {
        unsigned d = dilw(sE[R - 1][cc - 1], sE[R - 1][cc], sE[R - 1][cc + 1])
                   | dilw(sE[R][cc - 1],     v,             sE[R][cc + 1])
                   | dilw(sE[R + 1][cc - 1], sE[R + 1][cc], sE[R + 1][cc + 1]);
        unsigned nw = hclose(v | (Wm & d), Wm);
        int ch = (nw != v);
        if (ch) { v = nw; sE[R][cc] = v; }
        return __syncthreads_or(ch);
    };

    while (pass()) {}   // initial local fixpoint

    for (int r = 0;; r++) {
        if (row == 0)        *(volatile unsigned*)&g_E[r0 * WW + c] = v;
        if (row == BAND - 1) *(volatile unsigned*)&g_E[(r0 + BAND - 1) * WW + c] = v;
        grid_barrier();

        if (blockIdx.x == 0 && tid == 0) g_flag3[(r + 1) % 3] = 0u;  // pre-reset
        if (r > 0) {
            unsigned f = *(volatile unsigned*)&g_flag3[(r - 1) % 3];
            if (!f) break;
        }

        if (tid < WW) {
            sE[0][tid + 1] = (r0 > 0) ? *(volatile unsigned*)&g_E[(r0 - 1) * WW + tid] : 0u;
            sE[BAND + 1][tid + 1] = (r0 + BAND < H_IMG)
                ? *(volatile unsigned*)&g_E[(r0 + BAND) * WW + tid] : 0u;
        }
        __syncthreads();

        int changed = pass();
        if (changed) {
            if (tid == 0) atomicOr(&g_flag3[r % 3], 1u);
            while (pass()) {}
        }
    }

    // =============== PHASE 3: double-buffered TMA writeout ===============
    // 8 chunks of 2 rows (16 KB/plane); wait_group 1 pipelines buffer reuse.
    for (int k = 0; k < 8; k++) {
        if (k >= 2 && tid == 0)
            asm volatile("cp.async.bulk.wait_group 1;" ::: "memory");
        __syncthreads();

        const int rb = k * 2;
        const int f = tid;                   // 1024 float4 per chunk
        const int rw = f >> 9, x4 = f & 511;
        unsigned w = sE[rb + rw + 1][1 + (x4 >> 3)];
        unsigned b = (w >> ((x4 & 7u) * 4u)) & 0xFu;
        float4 o;
        o.x = (b & 1u) ? 1.0f : 0.0f;
        o.y = (b & 2u) ? 1.0f : 0.0f;
        o.z = (b & 4u) ? 1.0f : 0.0f;
        o.w = (b & 8u) ? 1.0f : 0.0f;
        sbuf[k & 1][f] = o;
        __syncthreads();

        if (tid == 0) {
            asm volatile("fence.proxy.async.shared::cta;" ::: "memory");
            unsigned saddr = (unsigned)__cvta_generic_to_shared(&sbuf[k & 1][0]);
#pragma unroll
            for (int plane = 0; plane < 3; plane++) {
                float* dst = out + (size_t)plane * NPIX + (size_t)(r0 + rb) * W_IMG;
                asm volatile(
                    "cp.async.bulk.global.shared::cta.bulk_group [%0], [%1], %2;"
                    :: "l"(dst), "r"(saddr), "n"(2 * W_IMG * 4) : "memory");
            }
            asm volatile("cp.async.bulk.commit_group;" ::: "memory");
        }
    }
    if (tid == 0)
        asm volatile("cp.async.bulk.wait_group 0;" ::: "memory");
}

// ---------------------------------------------------------------------------
extern "C" void kernel_launch(void* const* d_in, const int* in_sizes, int n_in,
                              void* d_out, int out_size) {
    const float* x = (const float*)d_in[0];
    float* out = (float*)d_out;
    k_fused<<<NB, 1024>>>(x, out);
}